// round 3
// baseline (speedup 1.0000x reference)
#include <cuda_runtime.h>

// Problem constants (fixed shapes).
static constexpr int B_    = 4096;
static constexpr int NPRE  = 16384;
static constexpr int NPOST = 16384;
static constexpr int R_    = 32;
static constexpr int SPLITK = 64;
static constexpr int KRANGE = NPRE / SPLITK;   // 256
static constexpr int KCHUNK = 8;

// Scratch (no allocations allowed -> __device__ globals).
__device__ float g_Zpart[SPLITK * B_ * R_];  // 32 MB  [split][b][r]
__device__ float g_Zt[R_ * B_];              // 512 KB [r][b]
__device__ float g_Ut[R_ * NPOST];           // 2 MB   [r][n]

// Packed fp32 (Blackwell f32x2) helpers.
#define FFMA2(d, a, b, c) \
    asm("fma.rn.f32x2 %0, %1, %2, %3;" : "=l"(d) : "l"(a), "l"(b), "l"(c))
#define DUPF(d, s) \
    asm("mov.b64 %0, {%1, %1};" : "=l"(d) : "r"(__float_as_uint(s)))

using ull = unsigned long long;

// ---------------------------------------------------------------------------
// Kernel A: Zpart[split] = S[:,ksplit] @ V[ksplit,:]
// Block: 128 threads, tile 256 rows x 32 r. Micro-tile 8 rows x 8 r
// (acc = 8x4 f32x2). S staged transposed in smem; V staged; reg prefetch.
// ---------------------------------------------------------------------------
__global__ __launch_bounds__(128) void gemmA(const float* __restrict__ S,
                                             const float* __restrict__ V) {
    const int rowtile = blockIdx.x;          // 0..15
    const int split   = blockIdx.y;          // 0..63
    const int tid     = threadIdx.x;
    const int rg      = tid & 3;             // 4 r-groups of 8
    const int mg      = tid >> 2;            // 32 row-groups of 8
    const int rbase   = rg * 8;
    const int rowbase = mg * 8;

    __shared__ float sS[KCHUNK][264];        // [k][row], pad 8
    __shared__ float sV[KCHUNK][40];         // [k][r],   pad 8

    ull acc[8][4];
#pragma unroll
    for (int i = 0; i < 8; i++)
#pragma unroll
        for (int j = 0; j < 4; j++) acc[i][j] = 0ull;

    const int row0 = rowtile * 256;
    const int k0   = split * KRANGE;
    const int kend = k0 + KRANGE;

    // Staging geometry: kv in {0,4}, srow 0..63, rows srow + 64*i.
    const int kv   = (tid & 1) * 4;
    const int srow = tid >> 1;               // 0..63
    const int vk   = tid >> 3;               // 0..15 (only tid<64 used)
    const int vr   = (tid & 7) * 4;

    float4 pS[4];
    float4 pV;
#pragma unroll
    for (int i = 0; i < 4; i++)
        pS[i] = *reinterpret_cast<const float4*>(
            &S[(size_t)(row0 + srow + 64 * i) * NPRE + k0 + kv]);
    if (tid < 64)
        pV = *reinterpret_cast<const float4*>(&V[(size_t)(k0 + vk) * R_ + vr]);

    for (int kb = k0; kb < kend; kb += KCHUNK) {
        __syncthreads();
#pragma unroll
        for (int i = 0; i < 4; i++) {
            int r = srow + 64 * i;
            sS[kv + 0][r] = pS[i].x;
            sS[kv + 1][r] = pS[i].y;
            sS[kv + 2][r] = pS[i].z;
            sS[kv + 3][r] = pS[i].w;
        }
        if (tid < 64)
            *reinterpret_cast<float4*>(&sV[vk][vr]) = pV;
        __syncthreads();

        const int kn = kb + KCHUNK;
        if (kn < kend) {
#pragma unroll
            for (int i = 0; i < 4; i++)
                pS[i] = *reinterpret_cast<const float4*>(
                    &S[(size_t)(row0 + srow + 64 * i) * NPRE + kn + kv]);
            if (tid < 64)
                pV = *reinterpret_cast<const float4*>(&V[(size_t)(kn + vk) * R_ + vr]);
        }

#pragma unroll
        for (int kk = 0; kk < KCHUNK; kk++) {
            // v: 8 r values = 4 f32x2 (pairs along r, contiguous).
            ulonglong2 va = *reinterpret_cast<const ulonglong2*>(&sV[kk][rbase]);
            ulonglong2 vb = *reinterpret_cast<const ulonglong2*>(&sV[kk][rbase + 4]);
            ull vv[4] = {va.x, va.y, vb.x, vb.y};
            // s: 8 row values, each duplicated into an f32x2.
            float4 sa = *reinterpret_cast<const float4*>(&sS[kk][rowbase]);
            float4 sb = *reinterpret_cast<const float4*>(&sS[kk][rowbase + 4]);
            float sf[8] = {sa.x, sa.y, sa.z, sa.w, sb.x, sb.y, sb.z, sb.w};
            ull sd[8];
#pragma unroll
            for (int i = 0; i < 8; i++) DUPF(sd[i], sf[i]);
#pragma unroll
            for (int i = 0; i < 8; i++)
#pragma unroll
                for (int j = 0; j < 4; j++)
                    FFMA2(acc[i][j], sd[i], vv[j], acc[i][j]);
        }
    }

    // Store partials: pairs along r are adjacent in memory.
    float* out = &g_Zpart[(size_t)split * B_ * R_];
#pragma unroll
    for (int i = 0; i < 8; i++) {
        float2 p0 = *reinterpret_cast<float2*>(&acc[i][0]);
        float2 p1 = *reinterpret_cast<float2*>(&acc[i][1]);
        float2 p2 = *reinterpret_cast<float2*>(&acc[i][2]);
        float2 p3 = *reinterpret_cast<float2*>(&acc[i][3]);
        float* row = &out[(size_t)(row0 + rowbase + i) * R_ + rbase];
        *reinterpret_cast<float4*>(row)     = make_float4(p0.x, p0.y, p1.x, p1.y);
        *reinterpret_cast<float4*>(row + 4) = make_float4(p2.x, p2.y, p3.x, p3.y);
    }
}

// ---------------------------------------------------------------------------
// Reduce split-K partials and transpose: g_Zt[r][b] = sum_s Zpart[s][b][r]
// ---------------------------------------------------------------------------
__global__ void reduceZ() {
    int g = blockIdx.x * blockDim.x + threadIdx.x;  // 0..131071
    int b = g >> 5;
    int r = g & 31;
    float s = 0.f;
#pragma unroll
    for (int sp = 0; sp < SPLITK; sp++)
        s += g_Zpart[(size_t)sp * B_ * R_ + (size_t)b * R_ + r];
    g_Zt[r * B_ + b] = s;
}

// ---------------------------------------------------------------------------
// Transpose U: g_Ut[r][n] = U[n][r]
// ---------------------------------------------------------------------------
__global__ void transU(const float* __restrict__ U) {
    int g = blockIdx.x * blockDim.x + threadIdx.x;  // 0..524287
    int r = g >> 14;
    int n = g & (NPOST - 1);
    g_Ut[g] = U[(size_t)n * R_ + r];
}

// ---------------------------------------------------------------------------
// Kernel B: Y[b][n] = sum_r Zt[r][b] * Ut[r][n]
// Block: 256 threads, tile 128 b x 128 n. Micro-tile 8b x 8n, f32x2 pairs
// along n (acc = 8x4 f32x2) -> vectorized coalesced stores.
// ---------------------------------------------------------------------------
__global__ __launch_bounds__(256) void gemmB(float* __restrict__ Y) {
    const int ntile = blockIdx.x;  // 0..127
    const int btile = blockIdx.y;  // 0..31
    const int tid   = threadIdx.x;
    const int tx    = tid & 15;    // n-group
    const int ty    = tid >> 4;    // b-group
    const int nb    = tx * 8;
    const int bb    = ty * 8;

    __shared__ float sZ[32][128];  // [r][b]  16 KB
    __shared__ float sU[32][128];  // [r][n]  16 KB

    const int b0 = btile * 128;
    const int n0 = ntile * 128;

#pragma unroll
    for (int i = 0; i < 4; i++) {
        int idx = tid + i * 256;    // 0..1023
        int r   = idx >> 5;
        int c   = (idx & 31) * 4;
        *reinterpret_cast<float4*>(&sZ[r][c]) =
            *reinterpret_cast<const float4*>(&g_Zt[r * B_ + b0 + c]);
        *reinterpret_cast<float4*>(&sU[r][c]) =
            *reinterpret_cast<const float4*>(&g_Ut[r * NPOST + n0 + c]);
    }
    __syncthreads();

    ull acc[8][4];
#pragma unroll
    for (int i = 0; i < 8; i++)
#pragma unroll
        for (int j = 0; j < 4; j++) acc[i][j] = 0ull;

#pragma unroll
    for (int r = 0; r < 32; r++) {
        // u: 8 n values = 4 f32x2 (pairs along n, contiguous).
        ulonglong2 ua = *reinterpret_cast<const ulonglong2*>(&sU[r][nb]);
        ulonglong2 ub = *reinterpret_cast<const ulonglong2*>(&sU[r][nb + 4]);
        ull uu[4] = {ua.x, ua.y, ub.x, ub.y};
        // z: 8 b values, each duplicated.
        float4 za = *reinterpret_cast<const float4*>(&sZ[r][bb]);
        float4 zb = *reinterpret_cast<const float4*>(&sZ[r][bb + 4]);
        float zf[8] = {za.x, za.y, za.z, za.w, zb.x, zb.y, zb.z, zb.w};
        ull zd[8];
#pragma unroll
        for (int i = 0; i < 8; i++) DUPF(zd[i], zf[i]);
#pragma unroll
        for (int i = 0; i < 8; i++)
#pragma unroll
            for (int j = 0; j < 4; j++)
                FFMA2(acc[i][j], zd[i], uu[j], acc[i][j]);
    }

    // Store: pairs along n are adjacent -> two float4 per output row.
#pragma unroll
    for (int i = 0; i < 8; i++) {
        float2 p0 = *reinterpret_cast<float2*>(&acc[i][0]);
        float2 p1 = *reinterpret_cast<float2*>(&acc[i][1]);
        float2 p2 = *reinterpret_cast<float2*>(&acc[i][2]);
        float2 p3 = *reinterpret_cast<float2*>(&acc[i][3]);
        float* yrow = &Y[(size_t)(b0 + bb + i) * NPOST + n0 + nb];
        *reinterpret_cast<float4*>(yrow)     = make_float4(p0.x, p0.y, p1.x, p1.y);
        *reinterpret_cast<float4*>(yrow + 4) = make_float4(p2.x, p2.y, p3.x, p3.y);
    }
}

// ---------------------------------------------------------------------------
// Entry point. Inputs: spikes, U, V, mask_* (masks unused by reference).
// ---------------------------------------------------------------------------
extern "C" void kernel_launch(void* const* d_in, const int* in_sizes, int n_in,
                              void* d_out, int out_size) {
    const float* spikes = (const float*)d_in[0];
    const float* U      = (const float*)d_in[1];
    const float* V      = (const float*)d_in[2];
    float* Y            = (float*)d_out;

    gemmA<<<dim3(B_ / 256, SPLITK), 128>>>(spikes, V);
    reduceZ<<<(B_ * R_) / 256, 256>>>();
    transU<<<(NPOST * R_) / 256, 256>>>(U);
    gemmB<<<dim3(NPOST / 128, B_ / 128), 256>>>(Y);
}